// round 6
// baseline (speedup 1.0000x reference)
#include <cuda_runtime.h>
#include <cuda_bf16.h>

// LDDMM variational evolve, Gaussian kernel sigma=0.1 (N=8192, D=3).
//   p      = clamp(mom, -1, 1)
//   K_ij   = exp(-50 |x_i - x_j|^2)     (exp2, expanded-distance form)
//   dcp_i  = sum_j K_ij p_j
//   dmom_i = 100 * ( x_i * sum_j W_ij - sum_j W_ij x_j ),  W_ij = K_ij (p_i.p_j)
//
// R6: single-resident-wave schedule. IPT=2, 64 thr/CTA, launch_bounds(64,14)
//     caps regs at 72 so all 2048 CTAs (13.84/SM) are resident at once --
//     R5's 112-reg version fit only 9/SM and paid a 1.45x two-wave penalty.
//     SPLITJ=32 halves partial traffic (8MB) for pass2.
// Pass 2: one warp per i, one split per lane, float4 coalesced + shfl reduce.

#define TI      64
#define IPT     2
#define IPB     (TI*IPT)   // 128 i's per block
#define JTILE   128
#define SPLITJ  32
#define MAXN    8192
#define L2E     1.4426950408889634f

typedef unsigned long long u64;

// partials: [i][split][8]  (7 used, padded to 8)
__device__ float g_part[MAXN * SPLITJ * 8];

__device__ __forceinline__ u64 pack2(float lo, float hi) {
    u64 r; asm("mov.b64 %0, {%1, %2};" : "=l"(r) : "f"(lo), "f"(hi)); return r;
}
__device__ __forceinline__ void unpack2(u64 v, float& lo, float& hi) {
    asm("mov.b64 {%0, %1}, %2;" : "=f"(lo), "=f"(hi) : "l"(v));
}
__device__ __forceinline__ u64 fma2(u64 a, u64 b, u64 c) {
    u64 d; asm("fma.rn.f32x2 %0, %1, %2, %3;" : "=l"(d) : "l"(a), "l"(b), "l"(c)); return d;
}
__device__ __forceinline__ u64 add2(u64 a, u64 b) {
    u64 d; asm("add.rn.f32x2 %0, %1, %2;" : "=l"(d) : "l"(a), "l"(b)); return d;
}
__device__ __forceinline__ float ex2a(float x) {
    float y; asm("ex2.approx.f32 %0, %1;" : "=f"(y) : "f"(x)); return y;
}
__device__ __forceinline__ float clamp1(float v) {
    return fminf(fmaxf(v, -1.f), 1.f);
}

__global__ void __launch_bounds__(TI, 14)
lddmm_pass1(const float* __restrict__ mom,
            const float* __restrict__ cp,
            int N)
{
    // per j: qa = { (xj.x,pj.x), (xj.y,pj.y) },  qb = { (xj.z,pj.z), (cj, 0) }
    __shared__ ulonglong2 sQa[JTILE];
    __shared__ ulonglong2 sQb[JTILE];

    const int jc = blockIdx.y;
    const int jchunk = N / SPLITJ;      // 256
    const int j0 = jc * jchunk;

    const float c100 = 100.0f * L2E;
    const float cm50 = -50.0f * L2E;

    u64 X0[IPT], X1[IPT], X2[IPT], AI[IPT];
    u64 acx[IPT], acy[IPT], acz[IPT];
    float row[IPT];

    #pragma unroll
    for (int q = 0; q < IPT; q++) {
        int i = blockIdx.x * IPB + q * TI + threadIdx.x;
        float xx = cp[3*i+0], xy = cp[3*i+1], xz = cp[3*i+2];
        float px = clamp1(mom[3*i+0]), py = clamp1(mom[3*i+1]), pz = clamp1(mom[3*i+2]);
        float sq = fmaf(xx, xx, fmaf(xy, xy, xz * xz));
        X0[q] = pack2(c100 * xx, px);
        X1[q] = pack2(c100 * xy, py);
        X2[q] = pack2(c100 * xz, pz);
        AI[q] = pack2(cm50 * sq, 0.0f);
        acx[q] = 0; acy[q] = 0; acz[q] = 0; row[q] = 0.f;
    }

    for (int jt = j0; jt < j0 + jchunk; jt += JTILE) {
        __syncthreads();
        #pragma unroll
        for (int t = threadIdx.x; t < JTILE; t += TI) {
            int j = jt + t;
            float ax = cp[3*j+0], ay = cp[3*j+1], az = cp[3*j+2];
            float bx = clamp1(mom[3*j+0]);
            float by = clamp1(mom[3*j+1]);
            float bz = clamp1(mom[3*j+2]);
            float cj = cm50 * fmaf(ax, ax, fmaf(ay, ay, az * az));
            sQa[t] = make_ulonglong2(pack2(ax, bx), pack2(ay, by));
            sQb[t] = make_ulonglong2(pack2(az, bz), pack2(cj, 0.0f));
        }
        __syncthreads();

        #pragma unroll 4
        for (int k = 0; k < JTILE; k++) {
            ulonglong2 qa = sQa[k];
            ulonglong2 qb = sQb[k];

            u64 acc[IPT];
            #pragma unroll
            for (int q = 0; q < IPT; q++) acc[q] = add2(qb.y, AI[q]);
            #pragma unroll
            for (int q = 0; q < IPT; q++) acc[q] = fma2(X0[q], qa.x, acc[q]);
            #pragma unroll
            for (int q = 0; q < IPT; q++) acc[q] = fma2(X1[q], qa.y, acc[q]);
            #pragma unroll
            for (int q = 0; q < IPT; q++) acc[q] = fma2(X2[q], qb.x, acc[q]);

            float K[IPT], w[IPT];
            #pragma unroll
            for (int q = 0; q < IPT; q++) {
                float arg, pd; unpack2(acc[q], arg, pd);
                K[q] = ex2a(arg);
                w[q] = K[q] * pd;
            }
            #pragma unroll
            for (int q = 0; q < IPT; q++) {
                u64 wK = pack2(w[q], K[q]);
                acx[q] = fma2(wK, qa.x, acx[q]);
                acy[q] = fma2(wK, qa.y, acy[q]);
                acz[q] = fma2(wK, qb.x, acz[q]);
                row[q] += w[q];
            }
        }
    }

    #pragma unroll
    for (int q = 0; q < IPT; q++) {
        int i = blockIdx.x * IPB + q * TI + threadIdx.x;
        float wxx, dcx, wxy, dcy, wxz, dcz;
        unpack2(acx[q], wxx, dcx);
        unpack2(acy[q], wxy, dcy);
        unpack2(acz[q], wxz, dcz);
        float4* p = (float4*)&g_part[(i * SPLITJ + jc) * 8];
        p[0] = make_float4(dcx, dcy, dcz, wxx);
        p[1] = make_float4(wxy, wxz, row[q], 0.0f);
    }
}

// One warp per i: one split per lane; coalesced float4 pairs + shfl reduce.
__global__ void __launch_bounds__(256)
lddmm_pass2(const float* __restrict__ cp,
            float* __restrict__ out,
            int N)
{
    int warp = (blockIdx.x * blockDim.x + threadIdx.x) >> 5;   // i index
    int lane = threadIdx.x & 31;
    if (warp >= N) return;
    int i = warp;

    const float4* p0 = (const float4*)&g_part[(i * SPLITJ + lane) * 8];
    float4 a = p0[0];   // dcx dcy dcz wxx
    float4 b = p0[1];   // wxy wxz row -

    #pragma unroll
    for (int d = 16; d > 0; d >>= 1) {
        a.x += __shfl_down_sync(0xffffffffu, a.x, d);
        a.y += __shfl_down_sync(0xffffffffu, a.y, d);
        a.z += __shfl_down_sync(0xffffffffu, a.z, d);
        a.w += __shfl_down_sync(0xffffffffu, a.w, d);
        b.x += __shfl_down_sync(0xffffffffu, b.x, d);
        b.y += __shfl_down_sync(0xffffffffu, b.y, d);
        b.z += __shfl_down_sync(0xffffffffu, b.z, d);
    }

    if (lane == 0) {
        float xix = cp[3*i+0], xiy = cp[3*i+1], xiz = cp[3*i+2];
        float rw = b.z;
        out[3*i+0] = 100.0f * fmaf(xix, rw, -a.w);
        out[3*i+1] = 100.0f * fmaf(xiy, rw, -b.x);
        out[3*i+2] = 100.0f * fmaf(xiz, rw, -b.y);
        out[3*N + 3*i+0] = a.x;
        out[3*N + 3*i+1] = a.y;
        out[3*N + 3*i+2] = a.z;
    }
}

extern "C" void kernel_launch(void* const* d_in, const int* in_sizes, int n_in,
                              void* d_out, int out_size)
{
    const float* mom = (const float*)d_in[0];
    const float* cp  = (const float*)d_in[1];
    float* out = (float*)d_out;
    int N = in_sizes[0] / 3;   // 8192

    dim3 g1(N / IPB, SPLITJ);  // 64 x 32 = 2048 CTAs, all resident in one wave
    lddmm_pass1<<<g1, TI>>>(mom, cp, N);

    int threads = N * 32;      // one warp per i
    lddmm_pass2<<<threads / 256, 256>>>(cp, out, N);
}